// round 14
// baseline (speedup 1.0000x reference)
#include <cuda_runtime.h>
#include <cstdint>

#define C_       256
#define NBOX_    1024
#define THREADS_ 512
#define NCP_     128          // f32x2 channel-pairs per pixel
#define MAXDY_   14
#define SMEMX_   (MAXDY_ * 7 * NCP_ * 8)   // 100352 bytes

typedef unsigned long long u64;

__device__ __forceinline__ u64 fma2(u64 a, u64 b, u64 c) {
    u64 d; asm("fma.rn.f32x2 %0,%1,%2,%3;" : "=l"(d) : "l"(a), "l"(b), "l"(c)); return d;
}
__device__ __forceinline__ u64 mul2(u64 a, u64 b) {
    u64 d; asm("mul.rn.f32x2 %0,%1,%2;" : "=l"(d) : "l"(a), "l"(b)); return d;
}
__device__ __forceinline__ u64 bcast2(float w) {
    return (u64)__float_as_uint(w) * 0x100000001ULL;
}
__device__ __forceinline__ void stcs64(void* p, u64 v) {
    asm volatile("st.global.cs.b64 [%0],%1;" :: "l"(p), "l"(v) : "memory");
}

__global__ __launch_bounds__(THREADS_, 2) void roialign_kernel(
    const float* __restrict__ feat0,
    const float* __restrict__ feat1,
    const float* __restrict__ rois,
    float* __restrict__ out)
{
    extern __shared__ u64 sX[];            // [MAXDY_][7][NCP_]
    __shared__ int  s_xo0[7], s_xo1[7];    // x corner byte offsets
    __shared__ u64  s_ax[7], s_bx[7];      // packed x weights (vx folded)
    __shared__ int  s_yrow[MAXDY_];        // distinct row base byte offsets
    __shared__ int  s_i0[7], s_i1[7];      // pool-row -> distinct-row indices
    __shared__ u64  s_wyA[7], s_wyB[7];    // packed y weights (vy folded)
    __shared__ int  s_dy, s_lvl;

    int n = blockIdx.x;
    int t = threadIdx.x;

    const float* roi = rois + (size_t)n * 5;
    float y1 = roi[0], x1 = roi[1], y2 = roi[2], x2 = roi[3];
    bool L = ((y2 - y1) > 48.0f) || ((x2 - x1) > 48.0f);
    int H = L ? 128 : 256;
    float Hm1 = (float)(H - 1);
    int b = n >> 9;
    const float inv = 1.0f / 1024.0f;

    // ---- x setup: 7 threads ----
    if (t < 7) {
        if (t == 0) s_lvl = L ? 1 : 0;
        float x1n = x1 * inv, x2n = x2 * inv;
        float xs = (x1n + (float)t * (1.0f / 6.0f) * (x2n - x1n)) * Hm1;
        float vx = (xs >= 0.0f && xs <= Hm1) ? 1.0f : 0.0f;
        float xf = floorf(xs);
        float wx = xs - xf;
        int x0 = (int)fminf(fmaxf(xf, 0.0f), Hm1);
        int xp = min(x0 + 1, H - 1);
        s_xo0[t] = x0 * (C_ * 4);
        s_xo1[t] = xp * (C_ * 4);
        s_ax[t] = bcast2((1.0f - wx) * vx);
        s_bx[t] = bcast2(wx * vx);
    }

    // ---- y setup: one thread builds distinct-row list (rows monotonic) ----
    if (t == 32) {          // different warp than x-setup
        float y1n = y1 * inv, y2n = y2 * inv;
        int ylist[MAXDY_];
        int dy = 0;
        #pragma unroll
        for (int r = 0; r < 7; r++) {
            float ys = (y1n + (float)r * (1.0f / 6.0f) * (y2n - y1n)) * Hm1;
            float vy = (ys >= 0.0f && ys <= Hm1) ? 1.0f : 0.0f;
            float yf = floorf(ys);
            float wy = ys - yf;
            int y0 = (int)fminf(fmaxf(yf, 0.0f), Hm1);
            int yp = min(y0 + 1, H - 1);

            int i0;
            if (dy > 0 && y0 == ylist[dy - 1])      i0 = dy - 1;
            else if (dy > 1 && y0 == ylist[dy - 2]) i0 = dy - 2;
            else { ylist[dy] = y0; i0 = dy; dy++; }

            int i1;
            if (yp == ylist[dy - 1]) i1 = dy - 1;
            else { ylist[dy] = yp; i1 = dy; dy++; }

            s_i0[r] = i0;
            s_i1[r] = i1;
            s_wyA[r] = bcast2((1.0f - wy) * vy);
            s_wyB[r] = bcast2(wy * vy);
        }
        s_dy = dy;
        for (int j = 0; j < dy; j++)
            s_yrow[j] = ((b * H + ylist[j]) * H) * (C_ * 4);
    }
    __syncthreads();

    int tcg  = t & (NCP_ - 1);   // channel pair 0..127
    int lane = t >> 7;           // 0..3
    int tp8  = tcg * 8;

    // ---- phase 1: x-interpolate distinct rows into smem ----
    const char* fb = (const char*)(s_lvl ? feat1 : feat0);
    int dy = s_dy;

    int xo0[7], xo1[7];
    #pragma unroll
    for (int c = 0; c < 7; c++) {
        xo0[c] = s_xo0[c] + tp8;
        xo1[c] = s_xo1[c] + tp8;
    }

    for (int j = lane; j < dy; j += 4) {
        const char* rb = fb + s_yrow[j];
        u64 p0[7], p1[7];
        #pragma unroll
        for (int c = 0; c < 7; c++) {
            p0[c] = __ldg((const u64*)(rb + xo0[c]));
            p1[c] = __ldg((const u64*)(rb + xo1[c]));
        }
        u64* xrow = &sX[(size_t)j * 7 * NCP_ + tcg];
        #pragma unroll
        for (int c = 0; c < 7; c++) {
            xrow[c * NCP_] = fma2(p1[c], s_bx[c], mul2(p0[c], s_ax[c]));
        }
    }
    __syncthreads();

    // ---- phase 2: y-blend from smem, store ----
    char* ob = (char*)out + (size_t)n * 49 * 1024 + tp8;

    for (int cell = lane; cell < 49; cell += 4) {
        int r = cell / 7;
        int c = cell - r * 7;
        u64 Xa = sX[(size_t)(s_i0[r] * 7 + c) * NCP_ + tcg];
        u64 Xb = sX[(size_t)(s_i1[r] * 7 + c) * NCP_ + tcg];
        u64 o = fma2(Xb, s_wyB[r], mul2(Xa, s_wyA[r]));
        stcs64(ob + (size_t)cell * 1024, o);
    }
}

extern "C" void kernel_launch(void* const* d_in, const int* in_sizes, int n_in,
                              void* d_out, int out_size)
{
    const float* feat0 = (const float*)d_in[0];
    const float* feat1 = (const float*)d_in[1];
    const float* rois  = (const float*)d_in[2];
    float* out = (float*)d_out;

    cudaFuncSetAttribute(roialign_kernel,
                         cudaFuncAttributeMaxDynamicSharedMemorySize, SMEMX_);
    roialign_kernel<<<NBOX_, THREADS_, SMEMX_>>>(feat0, feat1, rois, out);
}

// round 15
// speedup vs baseline: 1.0502x; 1.0502x over previous
#include <cuda_runtime.h>
#include <cstdint>

#define C_       256
#define NBOX_    1024
#define THREADS_ 512
#define MAXDY_   14
#define SMEMX_   (MAXDY_ * 7 * C_ * 4)   // 100352 bytes: X[j][7] pixels

typedef unsigned long long u64;

__device__ __forceinline__ u64 fma2(u64 a, u64 b, u64 c) {
    u64 d; asm("fma.rn.f32x2 %0,%1,%2,%3;" : "=l"(d) : "l"(a), "l"(b), "l"(c)); return d;
}
__device__ __forceinline__ u64 mul2(u64 a, u64 b) {
    u64 d; asm("mul.rn.f32x2 %0,%1,%2;" : "=l"(d) : "l"(a), "l"(b)); return d;
}
__device__ __forceinline__ u64 bcast2(float w) {
    return (u64)__float_as_uint(w) * 0x100000001ULL;
}
__device__ __forceinline__ u64 bcastf(float w) {
    u64 d; asm("mov.b64 %0,{%1,%1};" : "=l"(d) : "f"(w)); return d;
}
__device__ __forceinline__ void stcs64(void* p, u64 v) {
    asm volatile("st.global.cs.b64 [%0],%1;" :: "l"(p), "l"(v) : "memory");
}

__global__ __launch_bounds__(THREADS_, 2) void roialign_kernel(
    const float* __restrict__ feat0,
    const float* __restrict__ feat1,
    const float* __restrict__ rois,
    float* __restrict__ out)
{
    extern __shared__ ulonglong2 sX2[];      // [14*7][64] ulonglong2 (1KB/pixel)
    __shared__ int   s_xo0[7], s_xo1[7];     // x corner byte offsets
    __shared__ u64   s_ax[7], s_bx[7];       // packed x weights (vx folded)
    __shared__ int   s_yrow[MAXDY_];         // distinct row byte offsets
    __shared__ int   s_i0[7], s_i1[7];       // pool-row -> distinct-row index
    __shared__ float s_wyA[7], s_wyB[7];     // y weights (vy folded)
    __shared__ int4  s_cd[52];               // cell desc: {offA(u64), offB(u64), wAbits, wBbits}
    __shared__ int   s_dy;

    int n = blockIdx.x;
    int t = threadIdx.x;

    const float* roi = rois + (size_t)n * 5;
    float y1 = roi[0], x1 = roi[1], y2 = roi[2], x2 = roi[3];
    bool L = ((y2 - y1) > 48.0f) || ((x2 - x1) > 48.0f);
    int H = L ? 128 : 256;
    float Hm1 = (float)(H - 1);
    int b = n >> 9;
    const float inv = 1.0f / 1024.0f;

    // ---- x setup: threads 0..6 ----
    if (t < 7) {
        float x1n = x1 * inv, x2n = x2 * inv;
        float xs = (x1n + (float)t * (1.0f / 6.0f) * (x2n - x1n)) * Hm1;
        float vx = (xs >= 0.0f && xs <= Hm1) ? 1.0f : 0.0f;
        float xf = floorf(xs);
        float wx = xs - xf;
        int x0 = (int)fminf(fmaxf(xf, 0.0f), Hm1);
        int xp = min(x0 + 1, H - 1);
        s_xo0[t] = x0 * (C_ * 4);
        s_xo1[t] = xp * (C_ * 4);
        s_ax[t] = bcast2((1.0f - wx) * vx);
        s_bx[t] = bcast2(wx * vx);
    }

    // ---- y setup: one thread (separate warp) builds distinct-row list ----
    if (t == 32) {
        float y1n = y1 * inv, y2n = y2 * inv;
        int ylist[MAXDY_];
        int dy = 0;
        #pragma unroll
        for (int r = 0; r < 7; r++) {
            float ys = (y1n + (float)r * (1.0f / 6.0f) * (y2n - y1n)) * Hm1;
            float vy = (ys >= 0.0f && ys <= Hm1) ? 1.0f : 0.0f;
            float yf = floorf(ys);
            float wy = ys - yf;
            int y0 = (int)fminf(fmaxf(yf, 0.0f), Hm1);
            int yp = min(y0 + 1, H - 1);

            int i0;
            if (dy > 0 && y0 == ylist[dy - 1])      i0 = dy - 1;
            else if (dy > 1 && y0 == ylist[dy - 2]) i0 = dy - 2;
            else { ylist[dy] = y0; i0 = dy; dy++; }

            int i1;
            if (yp == ylist[dy - 1]) i1 = dy - 1;
            else { ylist[dy] = yp; i1 = dy; dy++; }

            s_i0[r] = i0;
            s_i1[r] = i1;
            s_wyA[r] = (1.0f - wy) * vy;
            s_wyB[r] = wy * vy;
        }
        s_dy = dy;
        for (int j = 0; j < dy; j++)
            s_yrow[j] = ((b * H + ylist[j]) * H) * (C_ * 4);
    }
    __syncthreads();

    // ---- build phase-2 descriptor table (threads 0..51) ----
    if (t < 52) {
        int4 d;
        if (t < 49) {
            int r = t / 7;
            int c = t - r * 7;
            d.x = (s_i0[r] * 7 + c) * 128;   // u64-unit smem offset
            d.y = (s_i1[r] * 7 + c) * 128;
            d.z = __float_as_int(s_wyA[r]);
            d.w = __float_as_int(s_wyB[r]);
        } else {
            d.x = 0; d.y = 0; d.z = 0; d.w = 0;
        }
        s_cd[t] = d;
    }

    // ---- phase 1: x-interpolate distinct rows into smem ----
    {
        int cg = t & 63;          // float4 group
        int jl = t >> 6;          // row lane 0..7
        const char* fb = (const char*)(L ? feat1 : feat0) + cg * 16;
        int dy = s_dy;

        for (int j = jl; j < dy; j += 8) {
            const char* rb = fb + s_yrow[j];
            ulonglong2 p0[7], p1[7];
            #pragma unroll
            for (int c = 0; c < 7; c++) {
                p0[c] = __ldg((const ulonglong2*)(rb + s_xo0[c]));
                p1[c] = __ldg((const ulonglong2*)(rb + s_xo1[c]));
            }
            ulonglong2* xr = &sX2[j * 7 * 64 + cg];
            #pragma unroll
            for (int c = 0; c < 7; c++) {
                u64 ax = s_ax[c], bx = s_bx[c];
                ulonglong2 X;
                X.x = fma2(p1[c].x, bx, mul2(p0[c].x, ax));
                X.y = fma2(p1[c].y, bx, mul2(p0[c].y, ax));
                xr[c * 64] = X;
            }
        }
    }
    __syncthreads();

    // ---- phase 2: y-blend from smem, store ----
    {
        int tcg  = t & 127;      // u64 channel pair
        int lane = t >> 7;       // 0..3
        const u64* sXu = (const u64*)sX2;
        char* ob = (char*)out + (size_t)n * 49 * 1024 + tcg * 8;

        #pragma unroll
        for (int k = 0; k < 13; k++) {
            int cell = lane + 4 * k;
            int4 d = s_cd[cell];
            u64 Xa = sXu[d.x + tcg];
            u64 Xb = sXu[d.y + tcg];
            u64 o = fma2(Xb, bcastf(__int_as_float(d.w)),
                         mul2(Xa, bcastf(__int_as_float(d.z))));
            if (cell < 49)
                stcs64(ob + cell * 1024, o);
        }
    }
}

extern "C" void kernel_launch(void* const* d_in, const int* in_sizes, int n_in,
                              void* d_out, int out_size)
{
    const float* feat0 = (const float*)d_in[0];
    const float* feat1 = (const float*)d_in[1];
    const float* rois  = (const float*)d_in[2];
    float* out = (float*)d_out;

    cudaFuncSetAttribute(roialign_kernel,
                         cudaFuncAttributeMaxDynamicSharedMemorySize, SMEMX_);
    roialign_kernel<<<NBOX_, THREADS_, SMEMX_>>>(feat0, feat1, rois, out);
}